// round 1
// baseline (speedup 1.0000x reference)
#include <cuda_runtime.h>
#include <math.h>

// Problem constants
#define Bsz 2
#define Nn  2048
#define Dd  1024
#define Hh  16
#define HDh 64
#define Rr  (Bsz * Nn)          // 4096 rows total

// Scratch (no allocation allowed -> device globals)
__device__ float g_hf[Rr * Dd];        // [4096,1024] per-head value features
__device__ float g_multi[Rr * Dd];     // [4096,1024] fused head outputs
__device__ float g_W12[Dd * Dd];       // out_proj @ o_proj
__device__ float g_partial[Bsz * 16 * Dd]; // partial column sums for mean
__device__ float g_c[Bsz * Hh * HDh];  // per-(b,head) folded bias

// -------------------------------------------------------------------------
// Generic fp32 GEMM: C[row0.., ccol0..] += A[M,K](lda) * B[K,?](ldb)
// Tile: BM=128, BN=64, BK=16; 256 threads; 8x4 register tile per thread.
// gridDim.z indexes an optional "head" dimension: B advances by strideBz,
// C columns advance by colOffZ. All dims assumed multiples of tile sizes.
// -------------------------------------------------------------------------
#define BM 128
#define BN 64
#define BK 16

__global__ __launch_bounds__(256) void gemm128x64(
    const float* __restrict__ A, const float* __restrict__ Bmat,
    float* __restrict__ C, int K, int lda, int ldb, int ldc,
    long strideBz, int colOffZ)
{
    __shared__ float As[BK][BM];   // A stored transposed
    __shared__ float Bs[BK][BN];

    const float* Bp = Bmat + (long)blockIdx.z * strideBz;
    const int row0  = blockIdx.y * BM;
    const int bcol0 = blockIdx.x * BN;                 // column within B
    const int ccol0 = bcol0 + blockIdx.z * colOffZ;    // column within C

    const int tid = threadIdx.x;
    const int tr  = tid >> 4;   // 0..15  (row group: 8 rows each)
    const int tc  = tid & 15;   // 0..15  (col group: 4 cols each)

    float acc[8][4];
#pragma unroll
    for (int i = 0; i < 8; i++)
#pragma unroll
        for (int j = 0; j < 4; j++) acc[i][j] = 0.0f;

    for (int kt = 0; kt < K; kt += BK) {
        // ---- load A tile (128x16) = 512 float4, 2 per thread, transpose ----
#pragma unroll
        for (int i = 0; i < 2; i++) {
            int idx = tid * 2 + i;          // 0..511
            int ar  = idx >> 2;             // row 0..127
            int aq  = idx & 3;              // float4 index along k
            float4 v = *(const float4*)(A + (long)(row0 + ar) * lda + kt + aq * 4);
            As[aq * 4 + 0][ar] = v.x;
            As[aq * 4 + 1][ar] = v.y;
            As[aq * 4 + 2][ar] = v.z;
            As[aq * 4 + 3][ar] = v.w;
        }
        // ---- load B tile (16x64) = 256 float4, 1 per thread ----
        {
            int br = tid >> 4;              // 0..15 (k row)
            int bq = tid & 15;              // 0..15 (col quad)
            float4 v = *(const float4*)(Bp + (long)(kt + br) * ldb + bcol0 + bq * 4);
            ((float4*)Bs[br])[bq] = v;
        }
        __syncthreads();

#pragma unroll
        for (int k = 0; k < BK; k++) {
            float4 a0 = ((float4*)As[k])[tr * 2 + 0];
            float4 a1 = ((float4*)As[k])[tr * 2 + 1];
            float4 b0 = ((float4*)Bs[k])[tc];
            float a[8] = {a0.x, a0.y, a0.z, a0.w, a1.x, a1.y, a1.z, a1.w};
            float b[4] = {b0.x, b0.y, b0.z, b0.w};
#pragma unroll
            for (int i = 0; i < 8; i++)
#pragma unroll
                for (int j = 0; j < 4; j++) acc[i][j] += a[i] * b[j];
        }
        __syncthreads();
    }

#pragma unroll
    for (int i = 0; i < 8; i++) {
        float4 v = make_float4(acc[i][0], acc[i][1], acc[i][2], acc[i][3]);
        *(float4*)(C + (long)(row0 + tr * 8 + i) * ldc + ccol0 + tc * 4) = v;
    }
}

// -------------------------------------------------------------------------
// Deterministic mean over sequence: stage 1 partial sums of 128 rows each.
// grid (16, B), block 1024: thread j sums column j over its 128-row chunk.
// -------------------------------------------------------------------------
__global__ __launch_bounds__(1024) void mean_partial_kernel()
{
    int j  = threadIdx.x;
    int nc = blockIdx.x;
    int b  = blockIdx.y;
    const float* base = g_hf + ((long)b * Nn + nc * 128) * Dd + j;
    float s = 0.0f;
#pragma unroll 8
    for (int n = 0; n < 128; n++) s += base[(long)n * Dd];
    g_partial[((long)b * 16 + nc) * Dd + j] = s;
}

// -------------------------------------------------------------------------
// Finalize mean and fold into per-(b,head) bias:
//   c[b,h,k] = fus_b1[h,k] + sum_m mean[b,h,m] * (w1[h,64+m,k] + w1[h,128+m,k])
// grid (H, B), block 64.
// -------------------------------------------------------------------------
__global__ __launch_bounds__(64) void compute_c_kernel(
    const float* __restrict__ fus_w1, const float* __restrict__ fus_b1)
{
    int hi = blockIdx.x, b = blockIdx.y, k = threadIdx.x;
    __shared__ float mean_s[HDh];

    float s = 0.0f;
    for (int nc = 0; nc < 16; nc++)
        s += g_partial[((long)b * 16 + nc) * Dd + hi * HDh + k];
    mean_s[k] = s * (1.0f / (float)Nn);
    __syncthreads();

    const float* w1 = fus_w1 + (long)hi * 192 * HDh;
    float acc = fus_b1[hi * HDh + k];
#pragma unroll 8
    for (int m = 0; m < HDh; m++)
        acc += mean_s[m] * (w1[(64 + m) * HDh + k] + w1[(128 + m) * HDh + k]);
    g_c[((long)b * Hh + hi) * HDh + k] = acc;
}

__device__ __forceinline__ float gelu_exact(float x)
{
    return 0.5f * x * (1.0f + erff(x * 0.70710678118654752440f));
}

// -------------------------------------------------------------------------
// Fused per-head relation MLP:
//   t  = gelu(hf_head @ w1[:64] + c[b,h])    (ff/bf contribution folded in c)
//   ho = t @ w2 + b2  -> multi[:, h*64:(h+1)*64]
// grid (R/32, H), block 256 (k = tid&63, row-group = tid>>6 covering 8 rows).
// -------------------------------------------------------------------------
__global__ __launch_bounds__(256) void fusion_kernel(
    const float* __restrict__ fus_w1, const float* __restrict__ fus_w2,
    const float* __restrict__ fus_b2)
{
    __shared__ float hfs[32][HDh];
    __shared__ float w1s[HDh][HDh];
    __shared__ float w2s[HDh][HDh];
    __shared__ float cs[HDh];
    __shared__ float b2s[HDh];

    const int hi = blockIdx.y;
    const int r0 = blockIdx.x * 32;
    const int b  = r0 / Nn;
    const int tid = threadIdx.x;

    const float* w1 = fus_w1 + (long)hi * 192 * HDh;  // first 64 rows used
    const float* w2 = fus_w2 + (long)hi * HDh * HDh;

#pragma unroll
    for (int i = 0; i < 16; i++) {
        int idx = tid + i * 256;              // 0..4095
        w1s[idx >> 6][idx & 63] = w1[idx];
        w2s[idx >> 6][idx & 63] = w2[idx];
    }
#pragma unroll
    for (int i = 0; i < 8; i++) {
        int idx = tid + i * 256;              // 0..2047
        int rl = idx >> 6, cm = idx & 63;
        hfs[rl][cm] = g_hf[(long)(r0 + rl) * Dd + hi * HDh + cm];
    }
    if (tid < HDh) {
        cs[tid]  = g_c[((long)b * Hh + hi) * HDh + tid];
        b2s[tid] = fus_b2[hi * HDh + tid];
    }
    __syncthreads();

    const int k  = tid & 63;
    const int rg = tid >> 6;                  // 0..3, 8 rows each

    float t[8];
#pragma unroll
    for (int i = 0; i < 8; i++) {
        int rl = rg * 8 + i;
        float acc = cs[k];
#pragma unroll 8
        for (int m = 0; m < HDh; m++) acc += hfs[rl][m] * w1s[m][k];
        t[i] = gelu_exact(acc);
    }
    __syncthreads();
    // reuse hfs as t storage
#pragma unroll
    for (int i = 0; i < 8; i++) hfs[rg * 8 + i][k] = t[i];
    __syncthreads();

#pragma unroll
    for (int i = 0; i < 8; i++) {
        int rl = rg * 8 + i;
        float acc = b2s[k];
#pragma unroll 8
        for (int j = 0; j < HDh; j++) acc += hfs[rl][j] * w2s[j][k];
        g_multi[(long)(r0 + rl) * Dd + hi * HDh + k] = acc;
    }
}

// -------------------------------------------------------------------------
// Tail outputs: main_fwd_ptr (constant 1023) and avg_strength (constant
// 1 - log(1/N + 1e-8)), only if the output buffer carries them.
// -------------------------------------------------------------------------
__global__ void tail_kernel(float* __restrict__ out, int out_size)
{
    const int base = Rr * Dd;
    int i = blockIdx.x * blockDim.x + threadIdx.x;
    if (out_size >= base + 2 * Rr) {
        float strength = 1.0f - logf(1.0f / (float)Nn + 1e-8f);
        if (i < Rr)            out[base + i] = 1023.0f;
        else if (i < 2 * Rr)   out[base + i] = strength;
    }
}

// -------------------------------------------------------------------------
extern "C" void kernel_launch(void* const* d_in, const int* in_sizes, int n_in,
                              void* d_out, int out_size)
{
    const float* h         = (const float*)d_in[0];
    // d_in[1..8]: fe/be scorer weights -> provably dead (uniform softmax)
    const float* vproj_w   = (const float*)d_in[9];
    const float* fus_w1    = (const float*)d_in[10];
    const float* fus_b1    = (const float*)d_in[11];
    const float* fus_w2    = (const float*)d_in[12];
    const float* fus_b2    = (const float*)d_in[13];
    const float* out_proj  = (const float*)d_in[14];
    const float* o_proj    = (const float*)d_in[15];
    float* z = (float*)d_out;

    float *hf_p, *multi_p, *W12_p;
    cudaGetSymbolAddress((void**)&hf_p,    g_hf);
    cudaGetSymbolAddress((void**)&multi_p, g_multi);
    cudaGetSymbolAddress((void**)&W12_p,   g_W12);

    // 1) hf = h @ vproj  (per-head [1024,64] blocks side by side)
    {
        dim3 grid(1, Rr / BM, Hh);
        gemm128x64<<<grid, 256>>>(h, vproj_w, hf_p,
                                  Dd, Dd, HDh, Dd,
                                  (long)Dd * HDh, HDh);
    }
    // 2) deterministic mean over sequence + folded bias c
    {
        dim3 grid(16, Bsz);
        mean_partial_kernel<<<grid, 1024>>>();
        dim3 gridc(Hh, Bsz);
        compute_c_kernel<<<gridc, 64>>>(fus_w1, fus_b1);
    }
    // 3) fused per-head relation MLP -> multi
    {
        dim3 grid(Rr / 32, Hh);
        fusion_kernel<<<grid, 256>>>(fus_w1, fus_w2, fus_b2);
    }
    // 4) W12 = out_proj @ o_proj  (fuses the two output projections)
    {
        dim3 grid(Dd / BN, Dd / BM, 1);
        gemm128x64<<<grid, 256>>>(out_proj, o_proj, W12_p,
                                  Dd, Dd, Dd, Dd, 0L, 0);
    }
    // 5) z = multi @ W12   (writes directly into d_out)
    {
        dim3 grid(Dd / BN, Rr / BM, 1);
        gemm128x64<<<grid, 256>>>(multi_p, W12_p, z,
                                  Dd, Dd, Dd, Dd, 0L, 0);
    }
    // 6) constant tail outputs (ptr = 1023, strength = 1 - log(1/N + 1e-8))
    tail_kernel<<<32, 256>>>(z, out_size);
}

// round 3
// speedup vs baseline: 2.1398x; 2.1398x over previous
#include <cuda_runtime.h>
#include <math.h>

// Problem constants
#define Bsz 2
#define Nn  2048
#define Dd  1024
#define Hh  16
#define HDh 64
#define Rr  (Bsz * Nn)          // 4096 rows total

// Scratch (no allocation allowed -> device globals)
__device__ float g_hf[Rr * Dd];        // [4096,1024] per-head value features
__device__ float g_multi[Rr * Dd];     // [4096,1024] fused head outputs
__device__ float g_W12[Dd * Dd];       // out_proj @ o_proj
__device__ float g_Vcat[Dd * Dd];      // vproj repacked [D, H*HD]
__device__ float g_partial[Bsz * 16 * Dd]; // partial column sums for mean
__device__ float g_c[Bsz * Hh * HDh];  // per-(b,head) folded bias

// =========================================================================
// tf32 mma.sync GEMM: C = A[M,K] * B[K,N], 128x128x32 tile, 256 thr (8 warps)
// warp tile 64x32, m16n8k8 fragments: 4 m-frags x 4 n-frags x 4 k-steps.
// All dims multiples of tile sizes. K multiple of 32.
// =========================================================================
__device__ __forceinline__ unsigned f2tf32(float v)
{
    unsigned o;
    asm volatile("cvt.rna.tf32.f32 %0, %1;\n" : "=r"(o) : "f"(v));
    return o;
}

__device__ __forceinline__ void mma_tf32(
    float& c0, float& c1, float& c2, float& c3,
    unsigned a0, unsigned a1, unsigned a2, unsigned a3,
    unsigned b0, unsigned b1)
{
    asm volatile(
        "mma.sync.aligned.m16n8k8.row.col.f32.tf32.tf32.f32 "
        "{%0,%1,%2,%3},{%4,%5,%6,%7},{%8,%9},{%0,%1,%2,%3};\n"
        : "+f"(c0), "+f"(c1), "+f"(c2), "+f"(c3)
        : "r"(a0), "r"(a1), "r"(a2), "r"(a3), "r"(b0), "r"(b1));
}

#define GBM 128
#define GBN 128
#define GBK 32
#define LDAS 132   // padded row length (uints)

__global__ __launch_bounds__(256) void gemm_tf32(
    const float* __restrict__ A, const float* __restrict__ Bmat,
    float* __restrict__ C, int K, int lda, int ldb, int ldc)
{
    __shared__ unsigned As[GBK][LDAS];   // [k][m]  (A transposed)
    __shared__ unsigned Bs[GBK][LDAS];   // [k][n]

    const int tid    = threadIdx.x;
    const int lane   = tid & 31;
    const int wid    = tid >> 5;
    const int warp_m = wid & 1;          // 0..1 -> 64 rows each
    const int warp_n = wid >> 1;         // 0..3 -> 32 cols each
    const int row0   = blockIdx.y * GBM;
    const int col0   = blockIdx.x * GBN;

    float acc[4][4][4];
#pragma unroll
    for (int i = 0; i < 4; i++)
#pragma unroll
        for (int j = 0; j < 4; j++)
#pragma unroll
            for (int q = 0; q < 4; q++) acc[i][j][q] = 0.0f;

    for (int kt = 0; kt < K; kt += GBK) {
        // ---- A tile: 128 rows x 32 k = 1024 float4, 4 per thread ----
#pragma unroll
        for (int i = 0; i < 4; i++) {
            int f = i * 256 + tid;            // 0..1023
            int r = f >> 3;                   // 0..127
            int q = f & 7;                    // float4 along k
            float4 v = *(const float4*)(A + (long)(row0 + r) * lda + kt + q * 4);
            As[q * 4 + 0][r] = f2tf32(v.x);
            As[q * 4 + 1][r] = f2tf32(v.y);
            As[q * 4 + 2][r] = f2tf32(v.z);
            As[q * 4 + 3][r] = f2tf32(v.w);
        }
        // ---- B tile: 32 k x 128 n = 1024 float4, 4 per thread ----
#pragma unroll
        for (int i = 0; i < 4; i++) {
            int f = i * 256 + tid;
            int kr = f >> 5;                  // 0..31
            int q  = f & 31;                  // float4 along n
            float4 v = *(const float4*)(Bmat + (long)(kt + kr) * ldb + col0 + q * 4);
            uint4 u;
            u.x = f2tf32(v.x); u.y = f2tf32(v.y);
            u.z = f2tf32(v.z); u.w = f2tf32(v.w);
            *(uint4*)&Bs[kr][q * 4] = u;
        }
        __syncthreads();

#pragma unroll
        for (int ks = 0; ks < 4; ks++) {
            const int k0 = ks * 8;
            unsigned a[4][4], b[4][2];
#pragma unroll
            for (int mi = 0; mi < 4; mi++) {
                int m0 = warp_m * 64 + mi * 16 + (lane >> 2);
                a[mi][0] = As[k0 + (lane & 3)][m0];
                a[mi][1] = As[k0 + (lane & 3)][m0 + 8];
                a[mi][2] = As[k0 + 4 + (lane & 3)][m0];
                a[mi][3] = As[k0 + 4 + (lane & 3)][m0 + 8];
            }
#pragma unroll
            for (int ni = 0; ni < 4; ni++) {
                int n0 = warp_n * 32 + ni * 8 + (lane >> 2);
                b[ni][0] = Bs[k0 + (lane & 3)][n0];
                b[ni][1] = Bs[k0 + 4 + (lane & 3)][n0];
            }
#pragma unroll
            for (int mi = 0; mi < 4; mi++)
#pragma unroll
                for (int ni = 0; ni < 4; ni++)
                    mma_tf32(acc[mi][ni][0], acc[mi][ni][1],
                             acc[mi][ni][2], acc[mi][ni][3],
                             a[mi][0], a[mi][1], a[mi][2], a[mi][3],
                             b[ni][0], b[ni][1]);
        }
        __syncthreads();
    }

#pragma unroll
    for (int mi = 0; mi < 4; mi++) {
        int r = row0 + warp_m * 64 + mi * 16 + (lane >> 2);
#pragma unroll
        for (int ni = 0; ni < 4; ni++) {
            int c = col0 + warp_n * 32 + ni * 8 + 2 * (lane & 3);
            *(float2*)(C + (long)r * ldc + c) =
                make_float2(acc[mi][ni][0], acc[mi][ni][1]);
            *(float2*)(C + (long)(r + 8) * ldc + c) =
                make_float2(acc[mi][ni][2], acc[mi][ni][3]);
        }
    }
}

// -------------------------------------------------------------------------
// Repack vproj [H][D][HD] -> Vcat [D][H*HD]
// -------------------------------------------------------------------------
__global__ __launch_bounds__(256) void repack_vcat(const float* __restrict__ vproj)
{
    int idx = blockIdx.x * 256 + threadIdx.x;   // 0..2^20-1
    int j = idx & 63;
    int k = (idx >> 6) & 1023;
    int h = idx >> 16;
    g_Vcat[(long)k * Dd + h * HDh + j] = vproj[idx];
}

// -------------------------------------------------------------------------
// Deterministic mean over sequence: stage 1 partial sums of 128 rows each.
// -------------------------------------------------------------------------
__global__ __launch_bounds__(1024) void mean_partial_kernel()
{
    int j  = threadIdx.x;
    int nc = blockIdx.x;
    int b  = blockIdx.y;
    const float* base = g_hf + ((long)b * Nn + nc * 128) * Dd + j;
    float s = 0.0f;
#pragma unroll 8
    for (int n = 0; n < 128; n++) s += base[(long)n * Dd];
    g_partial[((long)b * 16 + nc) * Dd + j] = s;
}

// -------------------------------------------------------------------------
// c[b,h,k] = fus_b1[h,k] + sum_m mean[b,h,m] * (w1[h,64+m,k] + w1[h,128+m,k])
// -------------------------------------------------------------------------
__global__ __launch_bounds__(64) void compute_c_kernel(
    const float* __restrict__ fus_w1, const float* __restrict__ fus_b1)
{
    int hi = blockIdx.x, b = blockIdx.y, k = threadIdx.x;
    __shared__ float mean_s[HDh];

    float s = 0.0f;
    for (int nc = 0; nc < 16; nc++)
        s += g_partial[((long)b * 16 + nc) * Dd + hi * HDh + k];
    mean_s[k] = s * (1.0f / (float)Nn);
    __syncthreads();

    const float* w1 = fus_w1 + (long)hi * 192 * HDh;
    float acc = fus_b1[hi * HDh + k];
#pragma unroll 8
    for (int m = 0; m < HDh; m++)
        acc += mean_s[m] * (w1[(64 + m) * HDh + k] + w1[(128 + m) * HDh + k]);
    g_c[((long)b * Hh + hi) * HDh + k] = acc;
}

__device__ __forceinline__ float gelu_exact(float x)
{
    return 0.5f * x * (1.0f + erff(x * 0.70710678118654752440f));
}

// -------------------------------------------------------------------------
// Fused per-head relation MLP, register-tiled 4x4:
//   t  = gelu(hf_head @ w1[:64] + c[b,h]);  ho = t @ w2 + b2
// Block: 64 rows x 64 cols (one head). 256 threads: 16x16 groups of 4x4.
// smem: hfs + w1s(+reused as t) + w2s = 3 * 16KB = 48KB.
// -------------------------------------------------------------------------
__global__ __launch_bounds__(256) void fusion_kernel(
    const float* __restrict__ fus_w1, const float* __restrict__ fus_w2,
    const float* __restrict__ fus_b2)
{
    __shared__ float hfs[HDh][HDh];
    __shared__ float w1s[HDh][HDh];   // reused as t after first layer
    __shared__ float w2s[HDh][HDh];

    const int hi = blockIdx.y;
    const int r0 = blockIdx.x * 64;
    const int b  = r0 / Nn;
    const int tid = threadIdx.x;
    const int tr = tid >> 4;          // 0..15, 4 rows each
    const int tc = tid & 15;          // 0..15, 4 cols each

    const float* w1 = fus_w1 + (long)hi * 192 * HDh;  // first 64 rows used
    const float* w2 = fus_w2 + (long)hi * HDh * HDh;

#pragma unroll
    for (int i = 0; i < 4; i++) {
        int f = i * 256 + tid;        // float4 index 0..1023
        int m = f >> 4, q = f & 15;
        *(float4*)&w1s[m][q * 4] = *(const float4*)(w1 + m * 64 + q * 4);
        *(float4*)&w2s[m][q * 4] = *(const float4*)(w2 + m * 64 + q * 4);
        int rl = f >> 4;
        *(float4*)&hfs[rl][q * 4] =
            *(const float4*)(g_hf + (long)(r0 + rl) * Dd + hi * HDh + q * 4);
    }
    float cv[4], b2v[4];
#pragma unroll
    for (int j = 0; j < 4; j++) {
        cv[j]  = g_c[((long)b * Hh + hi) * HDh + tc * 4 + j];
        b2v[j] = fus_b2[hi * HDh + tc * 4 + j];
    }
    __syncthreads();

    float acc[4][4];
#pragma unroll
    for (int i = 0; i < 4; i++)
#pragma unroll
        for (int j = 0; j < 4; j++) acc[i][j] = cv[j];

#pragma unroll 4
    for (int m = 0; m < HDh; m++) {
        float4 wv = *(float4*)&w1s[m][tc * 4];
        float hv[4];
#pragma unroll
        for (int i = 0; i < 4; i++) hv[i] = hfs[tr * 4 + i][m];
#pragma unroll
        for (int i = 0; i < 4; i++) {
            acc[i][0] += hv[i] * wv.x;
            acc[i][1] += hv[i] * wv.y;
            acc[i][2] += hv[i] * wv.z;
            acc[i][3] += hv[i] * wv.w;
        }
    }
    __syncthreads();   // everyone done reading w1s
#pragma unroll
    for (int i = 0; i < 4; i++)
#pragma unroll
        for (int j = 0; j < 4; j++)
            w1s[tr * 4 + i][tc * 4 + j] = gelu_exact(acc[i][j]);
    __syncthreads();

    float acc2[4][4];
#pragma unroll
    for (int i = 0; i < 4; i++)
#pragma unroll
        for (int j = 0; j < 4; j++) acc2[i][j] = b2v[j];

#pragma unroll 4
    for (int m = 0; m < HDh; m++) {
        float4 wv = *(float4*)&w2s[m][tc * 4];
        float tv[4];
#pragma unroll
        for (int i = 0; i < 4; i++) tv[i] = w1s[tr * 4 + i][m];
#pragma unroll
        for (int i = 0; i < 4; i++) {
            acc2[i][0] += tv[i] * wv.x;
            acc2[i][1] += tv[i] * wv.y;
            acc2[i][2] += tv[i] * wv.z;
            acc2[i][3] += tv[i] * wv.w;
        }
    }
#pragma unroll
    for (int i = 0; i < 4; i++) {
        float4 v = make_float4(acc2[i][0], acc2[i][1], acc2[i][2], acc2[i][3]);
        *(float4*)(g_multi + (long)(r0 + tr * 4 + i) * Dd + hi * HDh + tc * 4) = v;
    }
}

// -------------------------------------------------------------------------
// Tail outputs (constants), only if the output buffer carries them.
// -------------------------------------------------------------------------
__global__ void tail_kernel(float* __restrict__ out, int out_size)
{
    const int base = Rr * Dd;
    int i = blockIdx.x * blockDim.x + threadIdx.x;
    if (out_size >= base + 2 * Rr) {
        float strength = 1.0f - logf(1.0f / (float)Nn + 1e-8f);
        if (i < Rr)            out[base + i] = 1023.0f;
        else if (i < 2 * Rr)   out[base + i] = strength;
    }
}

// -------------------------------------------------------------------------
extern "C" void kernel_launch(void* const* d_in, const int* in_sizes, int n_in,
                              void* d_out, int out_size)
{
    const float* h         = (const float*)d_in[0];
    // d_in[1..8]: fe/be scorer weights -> provably dead (uniform softmax)
    const float* vproj_w   = (const float*)d_in[9];
    const float* fus_w1    = (const float*)d_in[10];
    const float* fus_b1    = (const float*)d_in[11];
    const float* fus_w2    = (const float*)d_in[12];
    const float* fus_b2    = (const float*)d_in[13];
    const float* out_proj  = (const float*)d_in[14];
    const float* o_proj    = (const float*)d_in[15];
    float* z = (float*)d_out;

    float *hf_p, *multi_p, *W12_p, *vcat_p;
    cudaGetSymbolAddress((void**)&hf_p,    g_hf);
    cudaGetSymbolAddress((void**)&multi_p, g_multi);
    cudaGetSymbolAddress((void**)&W12_p,   g_W12);
    cudaGetSymbolAddress((void**)&vcat_p,  g_Vcat);

    // 0) repack vproj into contiguous [D, D]
    repack_vcat<<<(Dd * Dd) / 256, 256>>>(vproj_w);

    // 1) hf = h @ Vcat  (tf32 tensor cores)
    {
        dim3 grid(Dd / GBN, Rr / GBM);
        gemm_tf32<<<grid, 256>>>(h, vcat_p, hf_p, Dd, Dd, Dd, Dd);
    }
    // 2) W12 = out_proj @ o_proj  (independent of hf)
    {
        dim3 grid(Dd / GBN, Dd / GBM);
        gemm_tf32<<<grid, 256>>>(out_proj, o_proj, W12_p, Dd, Dd, Dd, Dd);
    }
    // 3) deterministic mean over sequence + folded bias c
    {
        dim3 grid(16, Bsz);
        mean_partial_kernel<<<grid, 1024>>>();
        dim3 gridc(Hh, Bsz);
        compute_c_kernel<<<gridc, 64>>>(fus_w1, fus_b1);
    }
    // 4) fused per-head relation MLP -> multi
    {
        dim3 grid(Rr / 64, Hh);
        fusion_kernel<<<grid, 256>>>(fus_w1, fus_w2, fus_b2);
    }
    // 5) z = multi @ W12   (writes directly into d_out)
    {
        dim3 grid(Dd / GBN, Rr / GBM);
        gemm_tf32<<<grid, 256>>>(multi_p, W12_p, z, Dd, Dd, Dd, Dd);
    }
    // 6) constant tail outputs
    tail_kernel<<<32, 256>>>(z, out_size);
}